// round 10
// baseline (speedup 1.0000x reference)
#include <cuda_runtime.h>
#include <cuda.h>
#include <cuda_bf16.h>
#include <cuda_fp16.h>
#include <cstdint>

// Problem constants
#define B_   4
#define C_   8192
#define HW_  1024
#define D_   512
#define P_   (B_*HW_)          // 4096 positions (b*HW + hw)
#define NCHUNK 32
#define CPC  (C_/NCHUNK)       // 256 c per chunk

#define INV_TAU 1.1111111111111112f       // 1/0.9
#define LOGU   (-9.010913347279288f)      // log(1/8192)

// GEMM tiling: k-chunk = 64, A single fp16, B fp16 hi/lo
#define BM 128
#define BN 128
#define KB64 (C_/64)           // 128 chunks of k=64
#define KB32 (C_/32)           // 256 B k-blocks
#define A_TILE 16384           // 128 rows x 128B (64 fp16 = k64)
#define B_TILE 32768           // 128 rows x 2 x 128B (hi32|lo32 per kb32)
#define STAGE_B (A_TILE + B_TILE)   // 49152
#define NSTAGE 3
#define SMEM_GEMM (NSTAGE*STAGE_B + 1024)

// Packed scratch
__device__ __align__(1024) __half g_A[(size_t)P_ * C_];       // 64 MB [pos][kb64][64]
__device__ __align__(1024) __half g_B[(size_t)D_ * C_ * 2];   // 16 MB [d][kb32][hi32|lo32]
__device__ float g_part1[NCHUNK][P_];
__device__ float g_part2[NCHUNK][P_];
__device__ float g_s1inv[P_];
__device__ float g_logs2[P_];

// ---------------------------------------------------------------------------
// PTX helpers (sm_90-baseline only)
// ---------------------------------------------------------------------------
__device__ __forceinline__ uint32_t smem_u32(const void* p) {
    uint32_t a;
    asm("{ .reg .u64 t; cvta.to.shared.u64 t, %1; cvt.u32.u64 %0, t; }" : "=r"(a) : "l"(p));
    return a;
}
__device__ __forceinline__ void mbar_init(uint32_t a, uint32_t cnt) {
    asm volatile("mbarrier.init.shared.b64 [%0], %1;" :: "r"(a), "r"(cnt) : "memory");
}
__device__ __forceinline__ void mbar_wait(uint32_t a, uint32_t parity) {
    asm volatile("{\n\t.reg .pred P;\n\tWL%=:\n\t"
                 "mbarrier.try_wait.parity.acquire.cta.shared::cta.b64 P, [%0], %1, 0x989680;\n\t"
                 "@!P bra WL%=;\n\t}" :: "r"(a), "r"(parity) : "memory");
}
__device__ __forceinline__ void ldsm4(uint32_t* r, uint32_t a) {
    asm volatile("ldmatrix.sync.aligned.m8n8.x4.shared.b16 {%0,%1,%2,%3}, [%4];"
                 : "=r"(r[0]), "=r"(r[1]), "=r"(r[2]), "=r"(r[3]) : "r"(a));
}
__device__ __forceinline__ void mma16816(float* d, const uint32_t* a, const uint32_t* b) {
    asm volatile("mma.sync.aligned.m16n8k16.row.col.f32.f16.f16.f32 "
                 "{%0,%1,%2,%3}, {%4,%5,%6,%7}, {%8,%9}, {%0,%1,%2,%3};"
                 : "+f"(d[0]), "+f"(d[1]), "+f"(d[2]), "+f"(d[3])
                 : "r"(a[0]), "r"(a[1]), "r"(a[2]), "r"(a[3]), "r"(b[0]), "r"(b[1]));
}
__device__ __forceinline__ void tma_issue_pair(uint32_t mbar, uint32_t dstA, uint32_t dstB,
                                               const CUtensorMap* mA, const CUtensorMap* mB,
                                               int chunk, int m0, int n0) {
    asm volatile("mbarrier.arrive.expect_tx.shared.b64 _, [%0], %1;"
                 :: "r"(mbar), "r"((uint32_t)STAGE_B) : "memory");
    asm volatile("cp.async.bulk.tensor.3d.shared::cta.global.tile.mbarrier::complete_tx::bytes "
                 "[%0], [%1, {%2, %3, %4}], [%5];"
                 :: "r"(dstA), "l"(mA), "r"(0), "r"(chunk), "r"(m0), "r"(mbar) : "memory");
    asm volatile("cp.async.bulk.tensor.3d.shared::cta.global.tile.mbarrier::complete_tx::bytes "
                 "[%0], [%1, {%2, %3, %4}], [%5];"
                 :: "r"(dstB), "l"(mB), "r"(0), "r"(2 * chunk), "r"(n0), "r"(mbar) : "memory");
}

// ---------------------------------------------------------------------------
// Kernel 0: emb [c][d] fp32 -> g_B packed [d][kb32][hi32|lo32] fp16
// ---------------------------------------------------------------------------
__global__ void k_conv(const float* __restrict__ emb) {
    __shared__ float ts[32][33];
    int tx = threadIdx.x, ty = threadIdx.y;
    int c0 = blockIdx.x * 32, d0 = blockIdx.y * 32;
#pragma unroll
    for (int i = 0; i < 4; i++)
        ts[ty + 8 * i][tx] = emb[(size_t)(c0 + ty + 8 * i) * D_ + d0 + tx];
    __syncthreads();
    int kb = blockIdx.x;   // c0/32
#pragma unroll
    for (int i = 0; i < 4; i++) {
        int d = d0 + ty + 8 * i;
        float v = ts[tx][ty + 8 * i];
        __half h = __float2half(v);
        __half l = __float2half(v - __half2float(h));
        size_t idx = ((size_t)d * KB32 + kb) * 64 + tx;
        g_B[idx] = h;
        g_B[idx + 32] = l;
    }
}

// ---------------------------------------------------------------------------
// Kernel 1: partial sums per (position, c-chunk). No max-subtraction needed:
// (x+g)/tau <= ~27 -> exp fits fp32.
// ---------------------------------------------------------------------------
__global__ void k_stats(const float* __restrict__ x, const float* __restrict__ g) {
    int t = threadIdx.x;
    int pos = blockIdx.x * 256 + t;
    int chunk = blockIdx.y;
    int b = pos >> 10;
    int hw = pos & 1023;
    size_t base = ((size_t)b * C_ + (size_t)chunk * CPC) * HW_ + hw;
    const float* xp = x + base;
    const float* gp = g + base;
    float s1 = 0.f, s2 = 0.f;
#pragma unroll 8
    for (int c = 0; c < CPC; c++) {
        float xv = __ldg(xp + (size_t)c * HW_);
        float gv = __ldg(gp + (size_t)c * HW_);
        s1 += __expf((xv + gv) * INV_TAU);
        s2 += __expf(xv);
    }
    g_part1[chunk][pos] = s1;
    g_part2[chunk][pos] = s2;
}

__global__ void k_combine(float* klp) {
    int pos = blockIdx.x * 256 + threadIdx.x;
    float s1 = 0.f, s2 = 0.f;
#pragma unroll
    for (int k = 0; k < NCHUNK; k++) {
        s1 += g_part1[k][pos];
        s2 += g_part2[k][pos];
    }
    g_s1inv[pos] = 1.0f / s1;
    g_logs2[pos] = logf(s2);
    if (pos == 0 && klp) *klp = 0.0f;
}

// ---------------------------------------------------------------------------
// Kernel 2: transpose + elementwise. Writes logits/log_qy (scalar stores —
// base is odd-offset in d_out) and single-fp16 one_hot into g_A.
// ---------------------------------------------------------------------------
__global__ void k_elem(const float* __restrict__ x, const float* __restrict__ gm,
                       float* __restrict__ logits, float* __restrict__ logqy,
                       float* __restrict__ kl) {
    __shared__ __align__(16) float xs[32][66];
    __shared__ __align__(16) float gs[32][66];
    __shared__ float warpsum[8];

    int tx = threadIdx.x, ty = threadIdx.y;
    int t = ty * 32 + tx;
    int hw0 = blockIdx.x * 32;
    int c0  = blockIdx.y * 64;
    int b   = blockIdx.z;

#pragma unroll
    for (int i = 0; i < 8; i++) {
        int idx = t + 256 * i;
        int c = idx >> 5;
        int hw = idx & 31;
        size_t src = ((size_t)b * C_ + c0 + c) * HW_ + hw0 + hw;
        xs[hw][c] = x[src];
        gs[hw][c] = gm[src];
    }
    __syncthreads();

    int kb = blockIdx.y;   // c0/64

    float klacc = 0.f;
#pragma unroll
    for (int i = 0; i < 4; i++) {
        int hwl = ty + 8 * i;
        int pos = (b << 10) + hw0 + hwl;
        float ls2 = g_logs2[pos];
        float s1i = g_s1inv[pos];
        float2 xv = *(float2*)&xs[hwl][2 * tx];
        float2 gv = *(float2*)&gs[hwl][2 * tx];
        size_t o = (size_t)pos * C_ + c0 + 2 * tx;

        if (logits) { logits[o] = xv.x; logits[o + 1] = xv.y; }
        float lq0 = xv.x - ls2, lq1 = xv.y - ls2;
        if (logqy) { logqy[o] = lq0; logqy[o + 1] = lq1; }

        float p0 = __expf((xv.x + gv.x) * INV_TAU) * s1i;
        float p1 = __expf((xv.y + gv.y) * INV_TAU) * s1i;
        size_t pa = ((size_t)pos * KB64 + kb) * 64 + 2 * tx;
        __half2 hh; hh.x = __float2half(p0); hh.y = __float2half(p1);
        *(__half2*)(g_A + pa) = hh;

        klacc += __expf(lq0) * (lq0 - LOGU) + __expf(lq1) * (lq1 - LOGU);
    }

#pragma unroll
    for (int off = 16; off > 0; off >>= 1)
        klacc += __shfl_xor_sync(0xffffffffu, klacc, off);
    if (tx == 0) warpsum[ty] = klacc;
    __syncthreads();
    if (ty == 0 && tx < 8) {
        float v = warpsum[tx];
#pragma unroll
        for (int off = 4; off > 0; off >>= 1)
            v += __shfl_xor_sync(0xffu, v, off);
        if (tx == 0 && kl) atomicAdd(kl, v);
    }
}

// ---------------------------------------------------------------------------
// Kernel 3: mma.sync 2-product fp16 GEMM fed by TMA. k-chunk=64,
// 3-stage mbarrier pipeline with TMA issue hoisted before compute.
// 512 threads, 16 warps (4x4), 32x32 per warp.
// ---------------------------------------------------------------------------
__global__ void __launch_bounds__(512) k_gemm_tma(
    const __grid_constant__ CUtensorMap mapA,
    const __grid_constant__ CUtensorMap mapB,
    float* __restrict__ out) {
    extern __shared__ __align__(16) char sm[];
    __shared__ __align__(8) unsigned long long s_mbar[NSTAGE];

    uint32_t raw = smem_u32(sm);
    uint32_t base = (raw + 1023) & ~1023u;       // 1024-aligned for SW128
    uint32_t mb = smem_u32(s_mbar);

    int t = threadIdx.x, lid = t & 31, wid = t >> 5;
    int m0 = blockIdx.x * BM, n0 = blockIdx.y * BN;
    int wm = (wid >> 2) * 32, wn = (wid & 3) * 32;

    if (t == 0) {
#pragma unroll
        for (int s = 0; s < NSTAGE; s++) mbar_init(mb + 8 * s, 1);
    }
    asm volatile("fence.proxy.async.shared::cta;" ::: "memory");
    __syncthreads();

    // A lane constants: row r, swizzle by (r&7)
    uint32_t a0[2], swA[2];
#pragma unroll
    for (int mt = 0; mt < 2; mt++) {
        int r = wm + mt * 16 + (lid & 15);
        a0[mt] = (uint32_t)r * 128;
        swA[mt] = (uint32_t)(r & 7) << 4;
    }
    uint32_t cA = (uint32_t)(lid >> 4) << 4;

    // B lane constants: fill-row l = 2r+q; base r*256, swizzle (2r+q)&7
    uint32_t b0[2], swB[2][2];
#pragma unroll
    for (int jj = 0; jj < 2; jj++) {
        int r = wn + jj * 16 + ((lid >> 4) << 3) + (lid & 7);
        b0[jj] = (uint32_t)r * 256;
        swB[jj][0] = (uint32_t)((2 * r) & 7) << 4;
        swB[jj][1] = (uint32_t)((2 * r + 1) & 7) << 4;
    }
    uint32_t cB = (uint32_t)((lid >> 3) & 1) << 4;

    float acc[2][4][4];
#pragma unroll
    for (int i = 0; i < 2; i++)
#pragma unroll
        for (int j2 = 0; j2 < 4; j2++)
#pragma unroll
            for (int q = 0; q < 4; q++) acc[i][j2][q] = 0.f;

    if (t == 0) {
        tma_issue_pair(mb + 0, base, base + A_TILE, &mapA, &mapB, 0, m0, n0);
        tma_issue_pair(mb + 8, base + STAGE_B, base + STAGE_B + A_TILE,
                       &mapA, &mapB, 1, m0, n0);
    }

    int rd = 0, par = 0;
    for (int i = 0; i < KB64; i++) {
        mbar_wait(mb + 8 * rd, par);
        // Issue chunk i+2 into stage (rd+2)%NSTAGE — that buffer finished
        // consumption at iter i-1 (sealed by its trailing __syncthreads), so
        // the TMA gets ~2 compute windows to land.
        if (i + 2 < KB64 && t == 0) {
            int wr = rd + 2; if (wr >= NSTAGE) wr -= NSTAGE;
            uint32_t dA = base + (uint32_t)wr * STAGE_B;
            tma_issue_pair(mb + 8 * wr, dA, dA + A_TILE, &mapA, &mapB, i + 2, m0, n0);
        }
        uint32_t sA = base + (uint32_t)rd * STAGE_B;
        uint32_t sB = sA + A_TILE;
#pragma unroll
        for (int s = 0; s < 4; s++) {           // k-step of 16 within k=64
            uint32_t q = (uint32_t)(s >> 1);    // which kb32 sub-row
            uint32_t hb = (uint32_t)(s & 1) << 5;  // 0 or 32 bytes within half
            uint32_t av = (uint32_t)s << 5;     // A byte col = 32*s
            uint32_t a[2][4], bh[8], bl[8];
#pragma unroll
            for (int mt = 0; mt < 2; mt++)
                ldsm4(a[mt], sA + a0[mt] + ((cA + av) ^ swA[mt]));
#pragma unroll
            for (int jj = 0; jj < 2; jj++) {
                uint32_t rowb = sB + b0[jj] + q * 128;
                ldsm4(&bh[jj * 4], rowb + ((cB + hb) ^ swB[jj][q]));
                ldsm4(&bl[jj * 4], rowb + ((cB + hb + 64u) ^ swB[jj][q]));
            }
#pragma unroll
            for (int mt = 0; mt < 2; mt++)
#pragma unroll
                for (int nt = 0; nt < 4; nt++) {
                    mma16816(acc[mt][nt], a[mt], &bh[nt * 2]);
                    mma16816(acc[mt][nt], a[mt], &bl[nt * 2]);
                }
        }
        __syncthreads();   // seals this stage for reuse at iter i+1's issue
        rd++; if (rd == NSTAGE) { rd = 0; par ^= 1; }
    }

    // Epilogue: stage [n][m] in smem, then coalesced float4 stores along hw.
    float* so = (float*)sm;
    int g = lid >> 2, tt = lid & 3;
#pragma unroll
    for (int mt = 0; mt < 2; mt++)
#pragma unroll
        for (int nt = 0; nt < 4; nt++) {
            int nl = wn + nt * 8 + 2 * tt;
            int ml = wm + mt * 16 + g;
            so[nl * 128 + ml]           = acc[mt][nt][0];
            so[(nl + 1) * 128 + ml]     = acc[mt][nt][1];
            so[nl * 128 + ml + 8]       = acc[mt][nt][2];
            so[(nl + 1) * 128 + ml + 8] = acc[mt][nt][3];
        }
    __syncthreads();
    int bb = m0 >> 10, hw0 = m0 & 1023;
#pragma unroll
    for (int it = 0; it < 8; it++) {
        int idx = t + 512 * it;
        int n = idx >> 5, mq = (idx & 31) * 4;
        float4 v = *(float4*)&so[n * 128 + mq];
        *(float4*)&out[((size_t)bb * D_ + n0 + n) * HW_ + hw0 + mq] = v;
    }
}

// ---------------------------------------------------------------------------
// Launch. Output layout: sampled [B*D*HW] | kl [1] | logits [B*HW*C] | log_qy
// ---------------------------------------------------------------------------
typedef CUresult (*EncodeFn)(CUtensorMap*, CUtensorMapDataType, cuuint32_t, void*,
                             const cuuint64_t*, const cuuint64_t*, const cuuint32_t*,
                             const cuuint32_t*, CUtensorMapInterleave, CUtensorMapSwizzle,
                             CUtensorMapL2promotion, CUtensorMapFloatOOBfill);

extern "C" void kernel_launch(void* const* d_in, const int* in_sizes, int n_in,
                              void* d_out, int out_size) {
    const float* x   = (const float*)d_in[0];
    const float* gm  = (const float*)d_in[1];
    const float* emb = (const float*)d_in[2];
    float* out = (float*)d_out;

    const long long N_SAMP = (long long)B_ * D_ * HW_;
    const long long N_LG   = (long long)B_ * HW_ * C_;

    float* logits = nullptr;
    float* logqy  = nullptr;
    float* kl     = nullptr;
    if ((long long)out_size >= N_SAMP + 1 + 2 * N_LG) {
        kl     = out + N_SAMP;
        logits = out + N_SAMP + 1;
        logqy  = logits + N_LG;
    } else if ((long long)out_size >= N_SAMP + 1 + N_LG) {
        kl     = out + N_SAMP;
        logits = out + N_SAMP + 1;
    } else if ((long long)out_size >= N_SAMP + 1) {
        kl = out + N_SAMP;
    }

    static bool attr_done = false;
    if (!attr_done) {
        cudaFuncSetAttribute(k_gemm_tma, cudaFuncAttributeMaxDynamicSharedMemorySize,
                             SMEM_GEMM);
        attr_done = true;
    }

    // Build TMA descriptors (host-side, outside any graph node)
    EncodeFn enc = nullptr;
    cudaDriverEntryPointQueryResult qr;
    cudaGetDriverEntryPointByVersion("cuTensorMapEncodeTiled", (void**)&enc, 12000,
                                     cudaEnableDefault, &qr);
    void* pA = nullptr; void* pB = nullptr;
    cudaGetSymbolAddress(&pA, g_A);
    cudaGetSymbolAddress(&pB, g_B);

    CUtensorMap mA, mB;
    {   // A: [pos][kb64][64 fp16]
        cuuint64_t dims[3]   = {64, (cuuint64_t)KB64, (cuuint64_t)P_};
        cuuint64_t strides[2]= {128, (cuuint64_t)KB64 * 128};
        cuuint32_t box[3]    = {64, 1, BM};
        cuuint32_t es[3]     = {1, 1, 1};
        enc(&mA, CU_TENSOR_MAP_DATA_TYPE_FLOAT16, 3, pA, dims, strides, box, es,
            CU_TENSOR_MAP_INTERLEAVE_NONE, CU_TENSOR_MAP_SWIZZLE_128B,
            CU_TENSOR_MAP_L2_PROMOTION_L2_128B, CU_TENSOR_MAP_FLOAT_OOB_FILL_NONE);
    }
    {   // B: [d][kb32][hi32|lo32 fp16], box loads 2 kb per chunk
        cuuint64_t dims[3]   = {64, (cuuint64_t)KB32, (cuuint64_t)D_};
        cuuint64_t strides[2]= {128, (cuuint64_t)KB32 * 128};
        cuuint32_t box[3]    = {64, 2, BN};
        cuuint32_t es[3]     = {1, 1, 1};
        enc(&mB, CU_TENSOR_MAP_DATA_TYPE_FLOAT16, 3, pB, dims, strides, box, es,
            CU_TENSOR_MAP_INTERLEAVE_NONE, CU_TENSOR_MAP_SWIZZLE_128B,
            CU_TENSOR_MAP_L2_PROMOTION_L2_128B, CU_TENSOR_MAP_FLOAT_OOB_FILL_NONE);
    }

    k_conv<<<dim3(C_ / 32, D_ / 32), dim3(32, 8)>>>(emb);
    k_stats<<<dim3(16, NCHUNK), 256>>>(x, gm);
    k_combine<<<16, 256>>>(kl);
    k_elem<<<dim3(HW_ / 32, C_ / 64, B_), dim3(32, 8)>>>(x, gm, logits, logqy, kl);
    k_gemm_tma<<<dim3(P_ / BM, D_ / BN), 512, SMEM_GEMM>>>(mA, mB, out);
}

// round 11
// speedup vs baseline: 1.1760x; 1.1760x over previous
#include <cuda_runtime.h>
#include <cuda.h>
#include <cuda_bf16.h>
#include <cuda_fp16.h>
#include <cstdint>

// Problem constants
#define B_   4
#define C_   8192
#define HW_  1024
#define D_   512
#define P_   (B_*HW_)          // 4096 positions (b*HW + hw)
#define NCHUNK 32
#define CPC  (C_/NCHUNK)       // 256 c per chunk

#define INV_TAU 1.1111111111111112f       // 1/0.9
#define LOGU   (-9.010913347279288f)      // log(1/8192)

// GEMM tiling: k-chunk = 128, single fp16 product
#define BM 128
#define BN 128
#define KB64 (C_/64)           // 128 blocks of 64 (TMA row unit)
#define KB128 (C_/128)         // 64 k-chunks per CTA loop
#define A_TILE 32768           // 128 rows x 2 x 128B
#define B_TILE 32768
#define STAGE_B (A_TILE + B_TILE)   // 65536
#define NSTAGE 3
#define SMEM_GEMM (NSTAGE*STAGE_B + 1024)   // 197632

// Packed scratch: linear [row][C] fp16 (row-major k), 128B per kb64 block
__device__ __align__(1024) __half g_A[(size_t)P_ * C_];   // 64 MB
__device__ __align__(1024) __half g_B[(size_t)D_ * C_];   // 8 MB (L2-resident)
__device__ float g_part1[NCHUNK][P_];
__device__ float g_part2[NCHUNK][P_];
__device__ float g_s1inv[P_];
__device__ float g_logs2[P_];

// ---------------------------------------------------------------------------
// PTX helpers (sm_90-baseline only)
// ---------------------------------------------------------------------------
__device__ __forceinline__ uint32_t smem_u32(const void* p) {
    uint32_t a;
    asm("{ .reg .u64 t; cvta.to.shared.u64 t, %1; cvt.u32.u64 %0, t; }" : "=r"(a) : "l"(p));
    return a;
}
__device__ __forceinline__ void mbar_init(uint32_t a, uint32_t cnt) {
    asm volatile("mbarrier.init.shared.b64 [%0], %1;" :: "r"(a), "r"(cnt) : "memory");
}
__device__ __forceinline__ void mbar_wait(uint32_t a, uint32_t parity) {
    asm volatile("{\n\t.reg .pred P;\n\tWL%=:\n\t"
                 "mbarrier.try_wait.parity.acquire.cta.shared::cta.b64 P, [%0], %1, 0x989680;\n\t"
                 "@!P bra WL%=;\n\t}" :: "r"(a), "r"(parity) : "memory");
}
__device__ __forceinline__ void ldsm4(uint32_t* r, uint32_t a) {
    asm volatile("ldmatrix.sync.aligned.m8n8.x4.shared.b16 {%0,%1,%2,%3}, [%4];"
                 : "=r"(r[0]), "=r"(r[1]), "=r"(r[2]), "=r"(r[3]) : "r"(a));
}
__device__ __forceinline__ void mma16816(float* d, const uint32_t* a, const uint32_t* b) {
    asm volatile("mma.sync.aligned.m16n8k16.row.col.f32.f16.f16.f32 "
                 "{%0,%1,%2,%3}, {%4,%5,%6,%7}, {%8,%9}, {%0,%1,%2,%3};"
                 : "+f"(d[0]), "+f"(d[1]), "+f"(d[2]), "+f"(d[3])
                 : "r"(a[0]), "r"(a[1]), "r"(a[2]), "r"(a[3]), "r"(b[0]), "r"(b[1]));
}
__device__ __forceinline__ void tma_issue_pair(uint32_t mbar, uint32_t dstA, uint32_t dstB,
                                               const CUtensorMap* mA, const CUtensorMap* mB,
                                               int chunk, int m0, int n0) {
    asm volatile("mbarrier.arrive.expect_tx.shared.b64 _, [%0], %1;"
                 :: "r"(mbar), "r"((uint32_t)STAGE_B) : "memory");
    asm volatile("cp.async.bulk.tensor.3d.shared::cta.global.tile.mbarrier::complete_tx::bytes "
                 "[%0], [%1, {%2, %3, %4}], [%5];"
                 :: "r"(dstA), "l"(mA), "r"(0), "r"(2 * chunk), "r"(m0), "r"(mbar) : "memory");
    asm volatile("cp.async.bulk.tensor.3d.shared::cta.global.tile.mbarrier::complete_tx::bytes "
                 "[%0], [%1, {%2, %3, %4}], [%5];"
                 :: "r"(dstB), "l"(mB), "r"(0), "r"(2 * chunk), "r"(n0), "r"(mbar) : "memory");
}

// ---------------------------------------------------------------------------
// Kernel 0: emb [c][d] fp32 -> g_B [d][c] fp16 (transpose)
// ---------------------------------------------------------------------------
__global__ void k_conv(const float* __restrict__ emb) {
    __shared__ float ts[32][33];
    int tx = threadIdx.x, ty = threadIdx.y;
    int c0 = blockIdx.x * 32, d0 = blockIdx.y * 32;
#pragma unroll
    for (int i = 0; i < 4; i++)
        ts[ty + 8 * i][tx] = emb[(size_t)(c0 + ty + 8 * i) * D_ + d0 + tx];
    __syncthreads();
#pragma unroll
    for (int i = 0; i < 4; i++) {
        int d = d0 + ty + 8 * i;
        g_B[(size_t)d * C_ + c0 + tx] = __float2half(ts[tx][ty + 8 * i]);
    }
}

// ---------------------------------------------------------------------------
// Kernel 1: partial sums per (position, c-chunk). No max-subtraction needed:
// (x+g)/tau <= ~27 -> exp fits fp32.
// ---------------------------------------------------------------------------
__global__ void k_stats(const float* __restrict__ x, const float* __restrict__ g) {
    int t = threadIdx.x;
    int pos = blockIdx.x * 256 + t;
    int chunk = blockIdx.y;
    int b = pos >> 10;
    int hw = pos & 1023;
    size_t base = ((size_t)b * C_ + (size_t)chunk * CPC) * HW_ + hw;
    const float* xp = x + base;
    const float* gp = g + base;
    float s1 = 0.f, s2 = 0.f;
#pragma unroll 8
    for (int c = 0; c < CPC; c++) {
        float xv = __ldg(xp + (size_t)c * HW_);
        float gv = __ldg(gp + (size_t)c * HW_);
        s1 += __expf((xv + gv) * INV_TAU);
        s2 += __expf(xv);
    }
    g_part1[chunk][pos] = s1;
    g_part2[chunk][pos] = s2;
}

__global__ void k_combine(float* klp) {
    int pos = blockIdx.x * 256 + threadIdx.x;
    float s1 = 0.f, s2 = 0.f;
#pragma unroll
    for (int k = 0; k < NCHUNK; k++) {
        s1 += g_part1[k][pos];
        s2 += g_part2[k][pos];
    }
    g_s1inv[pos] = 1.0f / s1;
    g_logs2[pos] = logf(s2);
    if (pos == 0 && klp) *klp = 0.0f;
}

// ---------------------------------------------------------------------------
// Kernel 2: transpose + elementwise. Writes logits/log_qy (scalar stores —
// base is odd-offset in d_out) and fp16 one_hot into g_A [pos][c].
// ---------------------------------------------------------------------------
__global__ void k_elem(const float* __restrict__ x, const float* __restrict__ gm,
                       float* __restrict__ logits, float* __restrict__ logqy,
                       float* __restrict__ kl) {
    __shared__ __align__(16) float xs[32][66];
    __shared__ __align__(16) float gs[32][66];
    __shared__ float warpsum[8];

    int tx = threadIdx.x, ty = threadIdx.y;
    int t = ty * 32 + tx;
    int hw0 = blockIdx.x * 32;
    int c0  = blockIdx.y * 64;
    int b   = blockIdx.z;

#pragma unroll
    for (int i = 0; i < 8; i++) {
        int idx = t + 256 * i;
        int c = idx >> 5;
        int hw = idx & 31;
        size_t src = ((size_t)b * C_ + c0 + c) * HW_ + hw0 + hw;
        xs[hw][c] = x[src];
        gs[hw][c] = gm[src];
    }
    __syncthreads();

    float klacc = 0.f;
#pragma unroll
    for (int i = 0; i < 4; i++) {
        int hwl = ty + 8 * i;
        int pos = (b << 10) + hw0 + hwl;
        float ls2 = g_logs2[pos];
        float s1i = g_s1inv[pos];
        float2 xv = *(float2*)&xs[hwl][2 * tx];
        float2 gv = *(float2*)&gs[hwl][2 * tx];
        size_t o = (size_t)pos * C_ + c0 + 2 * tx;

        if (logits) { logits[o] = xv.x; logits[o + 1] = xv.y; }
        float lq0 = xv.x - ls2, lq1 = xv.y - ls2;
        if (logqy) { logqy[o] = lq0; logqy[o + 1] = lq1; }

        float p0 = __expf((xv.x + gv.x) * INV_TAU) * s1i;
        float p1 = __expf((xv.y + gv.y) * INV_TAU) * s1i;
        __half2 hh; hh.x = __float2half(p0); hh.y = __float2half(p1);
        *(__half2*)(g_A + o) = hh;

        klacc += __expf(lq0) * (lq0 - LOGU) + __expf(lq1) * (lq1 - LOGU);
    }

#pragma unroll
    for (int off = 16; off > 0; off >>= 1)
        klacc += __shfl_xor_sync(0xffffffffu, klacc, off);
    if (tx == 0) warpsum[ty] = klacc;
    __syncthreads();
    if (ty == 0 && tx < 8) {
        float v = warpsum[tx];
#pragma unroll
        for (int off = 4; off > 0; off >>= 1)
            v += __shfl_xor_sync(0xffu, v, off);
        if (tx == 0 && kl) atomicAdd(kl, v);
    }
}

// ---------------------------------------------------------------------------
// Kernel 3: mma.sync single-product fp16 GEMM fed by TMA. k-chunk=128,
// 3-stage mbarrier pipeline. 512 threads, 16 warps (4x4), 32x32 per warp.
// A and B share layout: TMA box {64,2,rows} -> fill-row l = 2r+q within tile,
// swizzle ((2r+q)&7)<<4, kstep byte col (s&3)<<5.
// ---------------------------------------------------------------------------
__global__ void __launch_bounds__(512) k_gemm_tma(
    const __grid_constant__ CUtensorMap mapA,
    const __grid_constant__ CUtensorMap mapB,
    float* __restrict__ out) {
    extern __shared__ __align__(16) char sm[];
    __shared__ __align__(8) unsigned long long s_mbar[NSTAGE];

    uint32_t raw = smem_u32(sm);
    uint32_t base = (raw + 1023) & ~1023u;       // 1024-aligned for SW128
    uint32_t mb = smem_u32(s_mbar);

    int t = threadIdx.x, lid = t & 31, wid = t >> 5;
    int m0 = blockIdx.x * BM, n0 = blockIdx.y * BN;
    int wm = (wid >> 2) * 32, wn = (wid & 3) * 32;

    if (t == 0) {
#pragma unroll
        for (int s = 0; s < NSTAGE; s++) mbar_init(mb + 8 * s, 1);
    }
    asm volatile("fence.proxy.async.shared::cta;" ::: "memory");
    __syncthreads();

    // A lane constants: row r -> tile base r*256, sub-row q adds q*128,
    // swizzle ((2r+q)&7)<<4
    uint32_t a0[2], swA[2][2];
#pragma unroll
    for (int mt = 0; mt < 2; mt++) {
        int r = wm + mt * 16 + (lid & 15);
        a0[mt] = (uint32_t)r * 256;
        swA[mt][0] = (uint32_t)((2 * r) & 7) << 4;
        swA[mt][1] = (uint32_t)((2 * r + 1) & 7) << 4;
    }
    uint32_t cA = (uint32_t)(lid >> 4) << 4;

    uint32_t b0[2], swB[2][2];
#pragma unroll
    for (int jj = 0; jj < 2; jj++) {
        int r = wn + jj * 16 + ((lid >> 4) << 3) + (lid & 7);
        b0[jj] = (uint32_t)r * 256;
        swB[jj][0] = (uint32_t)((2 * r) & 7) << 4;
        swB[jj][1] = (uint32_t)((2 * r + 1) & 7) << 4;
    }
    uint32_t cB = (uint32_t)((lid >> 3) & 1) << 4;

    float acc[2][4][4];
#pragma unroll
    for (int i = 0; i < 2; i++)
#pragma unroll
        for (int j2 = 0; j2 < 4; j2++)
#pragma unroll
            for (int q = 0; q < 4; q++) acc[i][j2][q] = 0.f;

    if (t == 0) {
#pragma unroll
        for (int s = 0; s < NSTAGE; s++) {
            uint32_t dA = base + (uint32_t)s * STAGE_B;
            tma_issue_pair(mb + 8 * s, dA, dA + A_TILE, &mapA, &mapB, s, m0, n0);
        }
    }

    int rd = 0, par = 0;
    for (int i = 0; i < KB128; i++) {
        mbar_wait(mb + 8 * rd, par);
        uint32_t sA = base + (uint32_t)rd * STAGE_B;
        uint32_t sB = sA + A_TILE;
#pragma unroll
        for (int s = 0; s < 8; s++) {           // 8 k-steps of 16 within k=128
            uint32_t q = (uint32_t)(s >> 2);    // which 64-k sub-row
            uint32_t av = (uint32_t)(s & 3) << 5;
            uint32_t a[2][4], bb[8];
#pragma unroll
            for (int mt = 0; mt < 2; mt++)
                ldsm4(a[mt], sA + a0[mt] + q * 128 + ((cA + av) ^ swA[mt][q]));
#pragma unroll
            for (int jj = 0; jj < 2; jj++)
                ldsm4(&bb[jj * 4], sB + b0[jj] + q * 128 + ((cB + av) ^ swB[jj][q]));
#pragma unroll
            for (int mt = 0; mt < 2; mt++)
#pragma unroll
                for (int nt = 0; nt < 4; nt++)
                    mma16816(acc[mt][nt], a[mt], &bb[nt * 2]);
        }
        __syncthreads();   // all warps done with stage rd
        if (i + NSTAGE < KB128 && t == 0) {
            uint32_t dA = base + (uint32_t)rd * STAGE_B;
            tma_issue_pair(mb + 8 * rd, dA, dA + A_TILE, &mapA, &mapB,
                           i + NSTAGE, m0, n0);
        }
        rd++; if (rd == NSTAGE) { rd = 0; par ^= 1; }
    }

    // Epilogue: stage [n][m] in smem, then coalesced float4 stores along hw.
    float* so = (float*)sm;
    int g = lid >> 2, tt = lid & 3;
#pragma unroll
    for (int mt = 0; mt < 2; mt++)
#pragma unroll
        for (int nt = 0; nt < 4; nt++) {
            int nl = wn + nt * 8 + 2 * tt;
            int ml = wm + mt * 16 + g;
            so[nl * 128 + ml]           = acc[mt][nt][0];
            so[(nl + 1) * 128 + ml]     = acc[mt][nt][1];
            so[nl * 128 + ml + 8]       = acc[mt][nt][2];
            so[(nl + 1) * 128 + ml + 8] = acc[mt][nt][3];
        }
    __syncthreads();
    int bb2 = m0 >> 10, hw0 = m0 & 1023;
#pragma unroll
    for (int it = 0; it < 8; it++) {
        int idx = t + 512 * it;
        int n = idx >> 5, mq = (idx & 31) * 4;
        float4 v = *(float4*)&so[n * 128 + mq];
        *(float4*)&out[((size_t)bb2 * D_ + n0 + n) * HW_ + hw0 + mq] = v;
    }
}

// ---------------------------------------------------------------------------
// Launch. Output layout: sampled [B*D*HW] | kl [1] | logits [B*HW*C] | log_qy
// ---------------------------------------------------------------------------
typedef CUresult (*EncodeFn)(CUtensorMap*, CUtensorMapDataType, cuuint32_t, void*,
                             const cuuint64_t*, const cuuint64_t*, const cuuint32_t*,
                             const cuuint32_t*, CUtensorMapInterleave, CUtensorMapSwizzle,
                             CUtensorMapL2promotion, CUtensorMapFloatOOBfill);

extern "C" void kernel_launch(void* const* d_in, const int* in_sizes, int n_in,
                              void* d_out, int out_size) {
    const float* x   = (const float*)d_in[0];
    const float* gm  = (const float*)d_in[1];
    const float* emb = (const float*)d_in[2];
    float* out = (float*)d_out;

    const long long N_SAMP = (long long)B_ * D_ * HW_;
    const long long N_LG   = (long long)B_ * HW_ * C_;

    float* logits = nullptr;
    float* logqy  = nullptr;
    float* kl     = nullptr;
    if ((long long)out_size >= N_SAMP + 1 + 2 * N_LG) {
        kl     = out + N_SAMP;
        logits = out + N_SAMP + 1;
        logqy  = logits + N_LG;
    } else if ((long long)out_size >= N_SAMP + 1 + N_LG) {
        kl     = out + N_SAMP;
        logits = out + N_SAMP + 1;
    } else if ((long long)out_size >= N_SAMP + 1) {
        kl = out + N_SAMP;
    }

    static bool attr_done = false;
    if (!attr_done) {
        cudaFuncSetAttribute(k_gemm_tma, cudaFuncAttributeMaxDynamicSharedMemorySize,
                             SMEM_GEMM);
        attr_done = true;
    }

    // Build TMA descriptors (host-side, outside any graph node)
    EncodeFn enc = nullptr;
    cudaDriverEntryPointQueryResult qr;
    cudaGetDriverEntryPointByVersion("cuTensorMapEncodeTiled", (void**)&enc, 12000,
                                     cudaEnableDefault, &qr);
    void* pA = nullptr; void* pB = nullptr;
    cudaGetSymbolAddress(&pA, g_A);
    cudaGetSymbolAddress(&pB, g_B);

    CUtensorMap mA, mB;
    {   // A: [pos][kb64][64 fp16], box loads 2 kb64 rows (k=128)
        cuuint64_t dims[3]   = {64, (cuuint64_t)KB64, (cuuint64_t)P_};
        cuuint64_t strides[2]= {128, (cuuint64_t)KB64 * 128};
        cuuint32_t box[3]    = {64, 2, BM};
        cuuint32_t es[3]     = {1, 1, 1};
        enc(&mA, CU_TENSOR_MAP_DATA_TYPE_FLOAT16, 3, pA, dims, strides, box, es,
            CU_TENSOR_MAP_INTERLEAVE_NONE, CU_TENSOR_MAP_SWIZZLE_128B,
            CU_TENSOR_MAP_L2_PROMOTION_L2_128B, CU_TENSOR_MAP_FLOAT_OOB_FILL_NONE);
    }
    {   // B: [d][kb64][64 fp16], box loads 2 kb64 rows (k=128)
        cuuint64_t dims[3]   = {64, (cuuint64_t)KB64, (cuuint64_t)D_};
        cuuint64_t strides[2]= {128, (cuuint64_t)KB64 * 128};
        cuuint32_t box[3]    = {64, 2, BN};
        cuuint32_t es[3]     = {1, 1, 1};
        enc(&mB, CU_TENSOR_MAP_DATA_TYPE_FLOAT16, 3, pB, dims, strides, box, es,
            CU_TENSOR_MAP_INTERLEAVE_NONE, CU_TENSOR_MAP_SWIZZLE_128B,
            CU_TENSOR_MAP_L2_PROMOTION_L2_128B, CU_TENSOR_MAP_FLOAT_OOB_FILL_NONE);
    }

    k_conv<<<dim3(C_ / 32, D_ / 32), dim3(32, 8)>>>(emb);
    k_stats<<<dim3(16, NCHUNK), 256>>>(x, gm);
    k_combine<<<16, 256>>>(kl);
    k_elem<<<dim3(HW_ / 32, C_ / 64, B_), dim3(32, 8)>>>(x, gm, logits, logqy, kl);
    k_gemm_tma<<<dim3(P_ / BM, D_ / BN), 512, SMEM_GEMM>>>(mA, mB, out);
}

// round 12
// speedup vs baseline: 1.3016x; 1.1067x over previous
#include <cuda_runtime.h>
#include <cuda.h>
#include <cuda_bf16.h>
#include <cuda_fp16.h>
#include <cstdint>

// Problem constants
#define B_   4
#define C_   8192
#define HW_  1024
#define D_   512
#define P_   (B_*HW_)          // 4096 positions (b*HW + hw)
#define NCHUNK 32
#define CPC  (C_/NCHUNK)       // 256 c per chunk

#define INV_TAU 1.1111111111111112f       // 1/0.9
#define LOGU   (-9.010913347279288f)      // log(1/8192)

// GEMM tiling: k-chunk = 128, single fp16 product, 8 warps of 64x32
#define BM 128
#define BN 128
#define KB64 (C_/64)           // 128 blocks of 64 (TMA row unit)
#define KB128 (C_/128)         // 64 k-chunks per CTA loop
#define A_TILE 32768           // 128 rows x 2 x 128B
#define B_TILE 32768
#define STAGE_B (A_TILE + B_TILE)   // 65536
#define NSTAGE 3
#define SMEM_GEMM (NSTAGE*STAGE_B + 1024)   // 197632

// Packed scratch: linear [row][C] fp16 (row-major k), 128B per kb64 block
__device__ __align__(1024) __half g_A[(size_t)P_ * C_];   // 64 MB
__device__ __align__(1024) __half g_B[(size_t)D_ * C_];   // 8 MB (L2-resident)
__device__ float g_part1[NCHUNK][P_];
__device__ float g_part2[NCHUNK][P_];
__device__ float g_s1inv[P_];
__device__ float g_logs2[P_];

// ---------------------------------------------------------------------------
// PTX helpers (sm_90-baseline only)
// ---------------------------------------------------------------------------
__device__ __forceinline__ uint32_t smem_u32(const void* p) {
    uint32_t a;
    asm("{ .reg .u64 t; cvta.to.shared.u64 t, %1; cvt.u32.u64 %0, t; }" : "=r"(a) : "l"(p));
    return a;
}
__device__ __forceinline__ void mbar_init(uint32_t a, uint32_t cnt) {
    asm volatile("mbarrier.init.shared.b64 [%0], %1;" :: "r"(a), "r"(cnt) : "memory");
}
__device__ __forceinline__ void mbar_wait(uint32_t a, uint32_t parity) {
    asm volatile("{\n\t.reg .pred P;\n\tWL%=:\n\t"
                 "mbarrier.try_wait.parity.acquire.cta.shared::cta.b64 P, [%0], %1, 0x989680;\n\t"
                 "@!P bra WL%=;\n\t}" :: "r"(a), "r"(parity) : "memory");
}
__device__ __forceinline__ void ldsm4(uint32_t* r, uint32_t a) {
    asm volatile("ldmatrix.sync.aligned.m8n8.x4.shared.b16 {%0,%1,%2,%3}, [%4];"
                 : "=r"(r[0]), "=r"(r[1]), "=r"(r[2]), "=r"(r[3]) : "r"(a));
}
__device__ __forceinline__ void mma16816(float* d, const uint32_t* a, const uint32_t* b) {
    asm volatile("mma.sync.aligned.m16n8k16.row.col.f32.f16.f16.f32 "
                 "{%0,%1,%2,%3}, {%4,%5,%6,%7}, {%8,%9}, {%0,%1,%2,%3};"
                 : "+f"(d[0]), "+f"(d[1]), "+f"(d[2]), "+f"(d[3])
                 : "r"(a[0]), "r"(a[1]), "r"(a[2]), "r"(a[3]), "r"(b[0]), "r"(b[1]));
}
__device__ __forceinline__ void tma_issue_pair(uint32_t mbar, uint32_t dstA, uint32_t dstB,
                                               const CUtensorMap* mA, const CUtensorMap* mB,
                                               int chunk, int m0, int n0) {
    asm volatile("mbarrier.arrive.expect_tx.shared.b64 _, [%0], %1;"
                 :: "r"(mbar), "r"((uint32_t)STAGE_B) : "memory");
    asm volatile("cp.async.bulk.tensor.3d.shared::cta.global.tile.mbarrier::complete_tx::bytes "
                 "[%0], [%1, {%2, %3, %4}], [%5];"
                 :: "r"(dstA), "l"(mA), "r"(0), "r"(2 * chunk), "r"(m0), "r"(mbar) : "memory");
    asm volatile("cp.async.bulk.tensor.3d.shared::cta.global.tile.mbarrier::complete_tx::bytes "
                 "[%0], [%1, {%2, %3, %4}], [%5];"
                 :: "r"(dstB), "l"(mB), "r"(0), "r"(2 * chunk), "r"(n0), "r"(mbar) : "memory");
}

// ---------------------------------------------------------------------------
// Kernel 0: emb [c][d] fp32 -> g_B [d][c] fp16 (transpose)
// ---------------------------------------------------------------------------
__global__ void k_conv(const float* __restrict__ emb) {
    __shared__ float ts[32][33];
    int tx = threadIdx.x, ty = threadIdx.y;
    int c0 = blockIdx.x * 32, d0 = blockIdx.y * 32;
#pragma unroll
    for (int i = 0; i < 4; i++)
        ts[ty + 8 * i][tx] = emb[(size_t)(c0 + ty + 8 * i) * D_ + d0 + tx];
    __syncthreads();
#pragma unroll
    for (int i = 0; i < 4; i++) {
        int d = d0 + ty + 8 * i;
        g_B[(size_t)d * C_ + c0 + tx] = __float2half(ts[tx][ty + 8 * i]);
    }
}

// ---------------------------------------------------------------------------
// Kernel 1: partial sums per (position, c-chunk). No max-subtraction needed:
// (x+g)/tau <= ~27 -> exp fits fp32.
// ---------------------------------------------------------------------------
__global__ void k_stats(const float* __restrict__ x, const float* __restrict__ g) {
    int t = threadIdx.x;
    int pos = blockIdx.x * 256 + t;
    int chunk = blockIdx.y;
    int b = pos >> 10;
    int hw = pos & 1023;
    size_t base = ((size_t)b * C_ + (size_t)chunk * CPC) * HW_ + hw;
    const float* xp = x + base;
    const float* gp = g + base;
    float s1 = 0.f, s2 = 0.f;
#pragma unroll 8
    for (int c = 0; c < CPC; c++) {
        float xv = __ldg(xp + (size_t)c * HW_);
        float gv = __ldg(gp + (size_t)c * HW_);
        s1 += __expf((xv + gv) * INV_TAU);
        s2 += __expf(xv);
    }
    g_part1[chunk][pos] = s1;
    g_part2[chunk][pos] = s2;
}

__global__ void k_combine(float* klp) {
    int pos = blockIdx.x * 256 + threadIdx.x;
    float s1 = 0.f, s2 = 0.f;
#pragma unroll
    for (int k = 0; k < NCHUNK; k++) {
        s1 += g_part1[k][pos];
        s2 += g_part2[k][pos];
    }
    g_s1inv[pos] = 1.0f / s1;
    g_logs2[pos] = logf(s2);
    if (pos == 0 && klp) *klp = 0.0f;
}

// ---------------------------------------------------------------------------
// Kernel 2: transpose + elementwise. Writes logits/log_qy (scalar stores —
// base is odd-offset in d_out) and fp16 one_hot into g_A [pos][c].
// ---------------------------------------------------------------------------
__global__ void k_elem(const float* __restrict__ x, const float* __restrict__ gm,
                       float* __restrict__ logits, float* __restrict__ logqy,
                       float* __restrict__ kl) {
    __shared__ __align__(16) float xs[32][66];
    __shared__ __align__(16) float gs[32][66];
    __shared__ float warpsum[8];

    int tx = threadIdx.x, ty = threadIdx.y;
    int t = ty * 32 + tx;
    int hw0 = blockIdx.x * 32;
    int c0  = blockIdx.y * 64;
    int b   = blockIdx.z;

#pragma unroll
    for (int i = 0; i < 8; i++) {
        int idx = t + 256 * i;
        int c = idx >> 5;
        int hw = idx & 31;
        size_t src = ((size_t)b * C_ + c0 + c) * HW_ + hw0 + hw;
        xs[hw][c] = x[src];
        gs[hw][c] = gm[src];
    }
    __syncthreads();

    float klacc = 0.f;
#pragma unroll
    for (int i = 0; i < 4; i++) {
        int hwl = ty + 8 * i;
        int pos = (b << 10) + hw0 + hwl;
        float ls2 = g_logs2[pos];
        float s1i = g_s1inv[pos];
        float2 xv = *(float2*)&xs[hwl][2 * tx];
        float2 gv = *(float2*)&gs[hwl][2 * tx];
        size_t o = (size_t)pos * C_ + c0 + 2 * tx;

        if (logits) { logits[o] = xv.x; logits[o + 1] = xv.y; }
        float lq0 = xv.x - ls2, lq1 = xv.y - ls2;
        if (logqy) { logqy[o] = lq0; logqy[o + 1] = lq1; }

        float p0 = __expf((xv.x + gv.x) * INV_TAU) * s1i;
        float p1 = __expf((xv.y + gv.y) * INV_TAU) * s1i;
        __half2 hh; hh.x = __float2half(p0); hh.y = __float2half(p1);
        *(__half2*)(g_A + o) = hh;

        klacc += __expf(lq0) * (lq0 - LOGU) + __expf(lq1) * (lq1 - LOGU);
    }

#pragma unroll
    for (int off = 16; off > 0; off >>= 1)
        klacc += __shfl_xor_sync(0xffffffffu, klacc, off);
    if (tx == 0) warpsum[ty] = klacc;
    __syncthreads();
    if (ty == 0 && tx < 8) {
        float v = warpsum[tx];
#pragma unroll
        for (int off = 4; off > 0; off >>= 1)
            v += __shfl_xor_sync(0xffu, v, off);
        if (tx == 0 && kl) atomicAdd(kl, v);
    }
}

// ---------------------------------------------------------------------------
// Kernel 3: mma.sync single-product fp16 GEMM fed by TMA. k-chunk=128,
// 3-stage mbarrier pipeline. 256 threads, 8 warps (2x4 grid), 64x32 per warp
// — wider M per warp cuts smem crossbar traffic 25% vs 32x32.
// ---------------------------------------------------------------------------
__global__ void __launch_bounds__(256) k_gemm_tma(
    const __grid_constant__ CUtensorMap mapA,
    const __grid_constant__ CUtensorMap mapB,
    float* __restrict__ out) {
    extern __shared__ __align__(16) char sm[];
    __shared__ __align__(8) unsigned long long s_mbar[NSTAGE];

    uint32_t raw = smem_u32(sm);
    uint32_t base = (raw + 1023) & ~1023u;       // 1024-aligned for SW128
    uint32_t mb = smem_u32(s_mbar);

    int t = threadIdx.x, lid = t & 31, wid = t >> 5;
    int m0 = blockIdx.x * BM, n0 = blockIdx.y * BN;
    int wm = (wid >> 2) * 64;    // warp m offset: 0 or 64
    int wn = (wid & 3) * 32;     // warp n offset: 0..96

    if (t == 0) {
#pragma unroll
        for (int s = 0; s < NSTAGE; s++) mbar_init(mb + 8 * s, 1);
    }
    asm volatile("fence.proxy.async.shared::cta;" ::: "memory");
    __syncthreads();

    // A lane constants: row r -> tile base r*256, sub-row q adds q*128,
    // swizzle ((2r+q)&7)<<4
    uint32_t a0[4], swA[4][2];
#pragma unroll
    for (int mt = 0; mt < 4; mt++) {
        int r = wm + mt * 16 + (lid & 15);
        a0[mt] = (uint32_t)r * 256;
        swA[mt][0] = (uint32_t)((2 * r) & 7) << 4;
        swA[mt][1] = (uint32_t)((2 * r + 1) & 7) << 4;
    }
    uint32_t cA = (uint32_t)(lid >> 4) << 4;

    uint32_t b0[2], swB[2][2];
#pragma unroll
    for (int jj = 0; jj < 2; jj++) {
        int r = wn + jj * 16 + ((lid >> 4) << 3) + (lid & 7);
        b0[jj] = (uint32_t)r * 256;
        swB[jj][0] = (uint32_t)((2 * r) & 7) << 4;
        swB[jj][1] = (uint32_t)((2 * r + 1) & 7) << 4;
    }
    uint32_t cB = (uint32_t)((lid >> 3) & 1) << 4;

    float acc[4][4][4];
#pragma unroll
    for (int i = 0; i < 4; i++)
#pragma unroll
        for (int j2 = 0; j2 < 4; j2++)
#pragma unroll
            for (int q = 0; q < 4; q++) acc[i][j2][q] = 0.f;

    if (t == 0) {
#pragma unroll
        for (int s = 0; s < NSTAGE; s++) {
            uint32_t dA = base + (uint32_t)s * STAGE_B;
            tma_issue_pair(mb + 8 * s, dA, dA + A_TILE, &mapA, &mapB, s, m0, n0);
        }
    }

    int rd = 0, par = 0;
    for (int i = 0; i < KB128; i++) {
        mbar_wait(mb + 8 * rd, par);
        uint32_t sA = base + (uint32_t)rd * STAGE_B;
        uint32_t sB = sA + A_TILE;
#pragma unroll
        for (int s = 0; s < 8; s++) {           // 8 k-steps of 16 within k=128
            uint32_t q = (uint32_t)(s >> 2);    // which 64-k sub-row
            uint32_t av = (uint32_t)(s & 3) << 5;
            uint32_t a[4][4], bb[8];
#pragma unroll
            for (int mt = 0; mt < 4; mt++)
                ldsm4(a[mt], sA + a0[mt] + q * 128 + ((cA + av) ^ swA[mt][q]));
#pragma unroll
            for (int jj = 0; jj < 2; jj++)
                ldsm4(&bb[jj * 4], sB + b0[jj] + q * 128 + ((cB + av) ^ swB[jj][q]));
#pragma unroll
            for (int mt = 0; mt < 4; mt++)
#pragma unroll
                for (int nt = 0; nt < 4; nt++)
                    mma16816(acc[mt][nt], a[mt], &bb[nt * 2]);
        }
        __syncthreads();   // all warps done with stage rd
        if (i + NSTAGE < KB128 && t == 0) {
            uint32_t dA = base + (uint32_t)rd * STAGE_B;
            tma_issue_pair(mb + 8 * rd, dA, dA + A_TILE, &mapA, &mapB,
                           i + NSTAGE, m0, n0);
        }
        rd++; if (rd == NSTAGE) { rd = 0; par ^= 1; }
    }

    // Epilogue: stage [n][m] in smem, then coalesced float4 stores along hw.
    float* so = (float*)sm;
    int g = lid >> 2, tt = lid & 3;
#pragma unroll
    for (int mt = 0; mt < 4; mt++)
#pragma unroll
        for (int nt = 0; nt < 4; nt++) {
            int nl = wn + nt * 8 + 2 * tt;
            int ml = wm + mt * 16 + g;
            so[nl * 128 + ml]           = acc[mt][nt][0];
            so[(nl + 1) * 128 + ml]     = acc[mt][nt][1];
            so[nl * 128 + ml + 8]       = acc[mt][nt][2];
            so[(nl + 1) * 128 + ml + 8] = acc[mt][nt][3];
        }
    __syncthreads();
    int bb2 = m0 >> 10, hw0 = m0 & 1023;
#pragma unroll
    for (int it = 0; it < 16; it++) {
        int idx = t + 256 * it;
        int n = idx >> 5, mq = (idx & 31) * 4;
        float4 v = *(float4*)&so[n * 128 + mq];
        *(float4*)&out[((size_t)bb2 * D_ + n0 + n) * HW_ + hw0 + mq] = v;
    }
}

// ---------------------------------------------------------------------------
// Launch. Output layout: sampled [B*D*HW] | kl [1] | logits [B*HW*C] | log_qy
// ---------------------------------------------------------------------------
typedef CUresult (*EncodeFn)(CUtensorMap*, CUtensorMapDataType, cuuint32_t, void*,
                             const cuuint64_t*, const cuuint64_t*, const cuuint32_t*,
                             const cuuint32_t*, CUtensorMapInterleave, CUtensorMapSwizzle,
                             CUtensorMapL2promotion, CUtensorMapFloatOOBfill);

extern "C" void kernel_launch(void* const* d_in, const int* in_sizes, int n_in,
                              void* d_out, int out_size) {
    const float* x   = (const float*)d_in[0];
    const float* gm  = (const float*)d_in[1];
    const float* emb = (const float*)d_in[2];
    float* out = (float*)d_out;

    const long long N_SAMP = (long long)B_ * D_ * HW_;
    const long long N_LG   = (long long)B_ * HW_ * C_;

    float* logits = nullptr;
    float* logqy  = nullptr;
    float* kl     = nullptr;
    if ((long long)out_size >= N_SAMP + 1 + 2 * N_LG) {
        kl     = out + N_SAMP;
        logits = out + N_SAMP + 1;
        logqy  = logits + N_LG;
    } else if ((long long)out_size >= N_SAMP + 1 + N_LG) {
        kl     = out + N_SAMP;
        logits = out + N_SAMP + 1;
    } else if ((long long)out_size >= N_SAMP + 1) {
        kl = out + N_SAMP;
    }

    static bool attr_done = false;
    if (!attr_done) {
        cudaFuncSetAttribute(k_gemm_tma, cudaFuncAttributeMaxDynamicSharedMemorySize,
                             SMEM_GEMM);
        attr_done = true;
    }

    // Build TMA descriptors (host-side, outside any graph node)
    EncodeFn enc = nullptr;
    cudaDriverEntryPointQueryResult qr;
    cudaGetDriverEntryPointByVersion("cuTensorMapEncodeTiled", (void**)&enc, 12000,
                                     cudaEnableDefault, &qr);
    void* pA = nullptr; void* pB = nullptr;
    cudaGetSymbolAddress(&pA, g_A);
    cudaGetSymbolAddress(&pB, g_B);

    CUtensorMap mA, mB;
    {   // A: [pos][kb64][64 fp16], box loads 2 kb64 rows (k=128)
        cuuint64_t dims[3]   = {64, (cuuint64_t)KB64, (cuuint64_t)P_};
        cuuint64_t strides[2]= {128, (cuuint64_t)KB64 * 128};
        cuuint32_t box[3]    = {64, 2, BM};
        cuuint32_t es[3]     = {1, 1, 1};
        enc(&mA, CU_TENSOR_MAP_DATA_TYPE_FLOAT16, 3, pA, dims, strides, box, es,
            CU_TENSOR_MAP_INTERLEAVE_NONE, CU_TENSOR_MAP_SWIZZLE_128B,
            CU_TENSOR_MAP_L2_PROMOTION_L2_128B, CU_TENSOR_MAP_FLOAT_OOB_FILL_NONE);
    }
    {   // B: [d][kb64][64 fp16], box loads 2 kb64 rows (k=128)
        cuuint64_t dims[3]   = {64, (cuuint64_t)KB64, (cuuint64_t)D_};
        cuuint64_t strides[2]= {128, (cuuint64_t)KB64 * 128};
        cuuint32_t box[3]    = {64, 2, BN};
        cuuint32_t es[3]     = {1, 1, 1};
        enc(&mB, CU_TENSOR_MAP_DATA_TYPE_FLOAT16, 3, pB, dims, strides, box, es,
            CU_TENSOR_MAP_INTERLEAVE_NONE, CU_TENSOR_MAP_SWIZZLE_128B,
            CU_TENSOR_MAP_L2_PROMOTION_L2_128B, CU_TENSOR_MAP_FLOAT_OOB_FILL_NONE);
    }

    k_conv<<<dim3(C_ / 32, D_ / 32), dim3(32, 8)>>>(emb);
    k_stats<<<dim3(16, NCHUNK), 256>>>(x, gm);
    k_combine<<<16, 256>>>(kl);
    k_elem<<<dim3(HW_ / 32, C_ / 64, B_), dim3(32, 8)>>>(x, gm, logits, logqy, kl);
    k_gemm_tma<<<dim3(P_ / BM, D_ / BN), 256, SMEM_GEMM>>>(mA, mB, out);
}

// round 13
// speedup vs baseline: 1.3100x; 1.0065x over previous
#include <cuda_runtime.h>
#include <cuda.h>
#include <cuda_bf16.h>
#include <cuda_fp16.h>
#include <cstdint>

// Problem constants
#define B_   4
#define C_   8192
#define HW_  1024
#define D_   512
#define P_   (B_*HW_)          // 4096 positions (b*HW + hw)
#define NCHUNK 32
#define CPC  (C_/NCHUNK)       // 256 c per chunk

#define INV_TAU 1.1111111111111112f       // 1/0.9
#define LOGU   (-9.010913347279288f)      // log(1/8192)

// GEMM tiling: k-chunk = 128, single fp16 product, 8 warps of 64x32
#define BM 128
#define BN 128
#define KB64 (C_/64)           // 128 blocks of 64 (TMA row unit)
#define KB128 (C_/128)         // 64 k-chunks per CTA loop
#define A_TILE 32768           // 128 rows x 2 x 128B
#define B_TILE 32768
#define STAGE_B (A_TILE + B_TILE)   // 65536
#define NSTAGE 3
#define SMEM_GEMM (NSTAGE*STAGE_B + 1024)   // 197632

// Packed scratch: linear [row][C] fp16 (row-major k), 128B per kb64 block
__device__ __align__(1024) __half g_A[(size_t)P_ * C_];   // 64 MB
__device__ __align__(1024) __half g_B[(size_t)D_ * C_];   // 8 MB (L2-resident)
__device__ float g_part1[NCHUNK][P_];
__device__ float g_part2[NCHUNK][P_];
__device__ float g_s1inv[P_];
__device__ float g_logs2[P_];

// ---------------------------------------------------------------------------
// PTX helpers (sm_90-baseline only)
// ---------------------------------------------------------------------------
__device__ __forceinline__ uint32_t smem_u32(const void* p) {
    uint32_t a;
    asm("{ .reg .u64 t; cvta.to.shared.u64 t, %1; cvt.u32.u64 %0, t; }" : "=r"(a) : "l"(p));
    return a;
}
__device__ __forceinline__ void mbar_init(uint32_t a, uint32_t cnt) {
    asm volatile("mbarrier.init.shared.b64 [%0], %1;" :: "r"(a), "r"(cnt) : "memory");
}
__device__ __forceinline__ void mbar_wait(uint32_t a, uint32_t parity) {
    asm volatile("{\n\t.reg .pred P;\n\tWL%=:\n\t"
                 "mbarrier.try_wait.parity.acquire.cta.shared::cta.b64 P, [%0], %1, 0x989680;\n\t"
                 "@!P bra WL%=;\n\t}" :: "r"(a), "r"(parity) : "memory");
}
__device__ __forceinline__ void ldsm4(uint32_t* r, uint32_t a) {
    asm volatile("ldmatrix.sync.aligned.m8n8.x4.shared.b16 {%0,%1,%2,%3}, [%4];"
                 : "=r"(r[0]), "=r"(r[1]), "=r"(r[2]), "=r"(r[3]) : "r"(a));
}
__device__ __forceinline__ void mma16816(float* d, const uint32_t* a, const uint32_t* b) {
    asm volatile("mma.sync.aligned.m16n8k16.row.col.f32.f16.f16.f32 "
                 "{%0,%1,%2,%3}, {%4,%5,%6,%7}, {%8,%9}, {%0,%1,%2,%3};"
                 : "+f"(d[0]), "+f"(d[1]), "+f"(d[2]), "+f"(d[3])
                 : "r"(a[0]), "r"(a[1]), "r"(a[2]), "r"(a[3]), "r"(b[0]), "r"(b[1]));
}
__device__ __forceinline__ void tma_issue_pair(uint32_t mbar, uint32_t dstA, uint32_t dstB,
                                               const CUtensorMap* mA, const CUtensorMap* mB,
                                               int chunk, int m0, int n0) {
    asm volatile("mbarrier.arrive.expect_tx.shared.b64 _, [%0], %1;"
                 :: "r"(mbar), "r"((uint32_t)STAGE_B) : "memory");
    asm volatile("cp.async.bulk.tensor.3d.shared::cta.global.tile.mbarrier::complete_tx::bytes "
                 "[%0], [%1, {%2, %3, %4}], [%5];"
                 :: "r"(dstA), "l"(mA), "r"(0), "r"(2 * chunk), "r"(m0), "r"(mbar) : "memory");
    asm volatile("cp.async.bulk.tensor.3d.shared::cta.global.tile.mbarrier::complete_tx::bytes "
                 "[%0], [%1, {%2, %3, %4}], [%5];"
                 :: "r"(dstB), "l"(mB), "r"(0), "r"(2 * chunk), "r"(n0), "r"(mbar) : "memory");
}

// ---------------------------------------------------------------------------
// Kernel 0: emb [c][d] fp32 -> g_B [d][c] fp16 (transpose)
// ---------------------------------------------------------------------------
__global__ void k_conv(const float* __restrict__ emb) {
    __shared__ float ts[32][33];
    int tx = threadIdx.x, ty = threadIdx.y;
    int c0 = blockIdx.x * 32, d0 = blockIdx.y * 32;
#pragma unroll
    for (int i = 0; i < 4; i++)
        ts[ty + 8 * i][tx] = emb[(size_t)(c0 + ty + 8 * i) * D_ + d0 + tx];
    __syncthreads();
#pragma unroll
    for (int i = 0; i < 4; i++) {
        int d = d0 + ty + 8 * i;
        g_B[(size_t)d * C_ + c0 + tx] = __float2half(ts[tx][ty + 8 * i]);
    }
}

// ---------------------------------------------------------------------------
// Kernel 1: partial sums per (position, c-chunk). No max-subtraction needed:
// (x+g)/tau <= ~27 -> exp fits fp32.
// ---------------------------------------------------------------------------
__global__ void k_stats(const float* __restrict__ x, const float* __restrict__ g) {
    int t = threadIdx.x;
    int pos = blockIdx.x * 256 + t;
    int chunk = blockIdx.y;
    int b = pos >> 10;
    int hw = pos & 1023;
    size_t base = ((size_t)b * C_ + (size_t)chunk * CPC) * HW_ + hw;
    const float* xp = x + base;
    const float* gp = g + base;
    float s1 = 0.f, s2 = 0.f;
#pragma unroll 8
    for (int c = 0; c < CPC; c++) {
        float xv = __ldg(xp + (size_t)c * HW_);
        float gv = __ldg(gp + (size_t)c * HW_);
        s1 += __expf((xv + gv) * INV_TAU);
        s2 += __expf(xv);
    }
    g_part1[chunk][pos] = s1;
    g_part2[chunk][pos] = s2;
}

__global__ void k_combine(float* klp) {
    int pos = blockIdx.x * 256 + threadIdx.x;
    float s1 = 0.f, s2 = 0.f;
#pragma unroll
    for (int k = 0; k < NCHUNK; k++) {
        s1 += g_part1[k][pos];
        s2 += g_part2[k][pos];
    }
    g_s1inv[pos] = 1.0f / s1;
    g_logs2[pos] = logf(s2);
    if (pos == 0 && klp) *klp = 0.0f;
}

// ---------------------------------------------------------------------------
// Kernel 2: transpose + elementwise. Writes logits/log_qy (scalar stores —
// base is odd-offset in d_out) and fp16 one_hot into g_A [pos][c].
// ---------------------------------------------------------------------------
__global__ void k_elem(const float* __restrict__ x, const float* __restrict__ gm,
                       float* __restrict__ logits, float* __restrict__ logqy,
                       float* __restrict__ kl) {
    __shared__ __align__(16) float xs[32][66];
    __shared__ __align__(16) float gs[32][66];
    __shared__ float warpsum[8];

    int tx = threadIdx.x, ty = threadIdx.y;
    int t = ty * 32 + tx;
    int hw0 = blockIdx.x * 32;
    int c0  = blockIdx.y * 64;
    int b   = blockIdx.z;

#pragma unroll
    for (int i = 0; i < 8; i++) {
        int idx = t + 256 * i;
        int c = idx >> 5;
        int hw = idx & 31;
        size_t src = ((size_t)b * C_ + c0 + c) * HW_ + hw0 + hw;
        xs[hw][c] = x[src];
        gs[hw][c] = gm[src];
    }
    __syncthreads();

    float klacc = 0.f;
#pragma unroll
    for (int i = 0; i < 4; i++) {
        int hwl = ty + 8 * i;
        int pos = (b << 10) + hw0 + hwl;
        float ls2 = g_logs2[pos];
        float s1i = g_s1inv[pos];
        float2 xv = *(float2*)&xs[hwl][2 * tx];
        float2 gv = *(float2*)&gs[hwl][2 * tx];
        size_t o = (size_t)pos * C_ + c0 + 2 * tx;

        if (logits) { logits[o] = xv.x; logits[o + 1] = xv.y; }
        float lq0 = xv.x - ls2, lq1 = xv.y - ls2;
        if (logqy) { logqy[o] = lq0; logqy[o + 1] = lq1; }

        float p0 = __expf((xv.x + gv.x) * INV_TAU) * s1i;
        float p1 = __expf((xv.y + gv.y) * INV_TAU) * s1i;
        __half2 hh; hh.x = __float2half(p0); hh.y = __float2half(p1);
        *(__half2*)(g_A + o) = hh;

        klacc += __expf(lq0) * (lq0 - LOGU) + __expf(lq1) * (lq1 - LOGU);
    }

#pragma unroll
    for (int off = 16; off > 0; off >>= 1)
        klacc += __shfl_xor_sync(0xffffffffu, klacc, off);
    if (tx == 0) warpsum[ty] = klacc;
    __syncthreads();
    if (ty == 0 && tx < 8) {
        float v = warpsum[tx];
#pragma unroll
        for (int off = 4; off > 0; off >>= 1)
            v += __shfl_xor_sync(0xffu, v, off);
        if (tx == 0 && kl) atomicAdd(kl, v);
    }
}

// ---------------------------------------------------------------------------
// Kernel 3: mma.sync single-product fp16 GEMM fed by TMA. k-chunk=128,
// 3-stage mbarrier pipeline. 256 threads, 8 warps (2x4 grid), 64x32 per warp.
// Register-double-buffered fragments: kstep s+1's ldsm issue BEFORE kstep s's
// mma burst so the crossbar runs under the tensor pipe.
// ---------------------------------------------------------------------------
__global__ void __launch_bounds__(256) k_gemm_tma(
    const __grid_constant__ CUtensorMap mapA,
    const __grid_constant__ CUtensorMap mapB,
    float* __restrict__ out) {
    extern __shared__ __align__(16) char sm[];
    __shared__ __align__(8) unsigned long long s_mbar[NSTAGE];

    uint32_t raw = smem_u32(sm);
    uint32_t base = (raw + 1023) & ~1023u;       // 1024-aligned for SW128
    uint32_t mb = smem_u32(s_mbar);

    int t = threadIdx.x, lid = t & 31, wid = t >> 5;
    int m0 = blockIdx.x * BM, n0 = blockIdx.y * BN;
    int wm = (wid >> 2) * 64;    // warp m offset: 0 or 64
    int wn = (wid & 3) * 32;     // warp n offset: 0..96

    if (t == 0) {
#pragma unroll
        for (int s = 0; s < NSTAGE; s++) mbar_init(mb + 8 * s, 1);
    }
    asm volatile("fence.proxy.async.shared::cta;" ::: "memory");
    __syncthreads();

    // A lane constants: row r -> tile base r*256, sub-row q adds q*128,
    // swizzle ((2r+q)&7)<<4
    uint32_t a0[4], swA[4][2];
#pragma unroll
    for (int mt = 0; mt < 4; mt++) {
        int r = wm + mt * 16 + (lid & 15);
        a0[mt] = (uint32_t)r * 256;
        swA[mt][0] = (uint32_t)((2 * r) & 7) << 4;
        swA[mt][1] = (uint32_t)((2 * r + 1) & 7) << 4;
    }
    uint32_t cA = (uint32_t)(lid >> 4) << 4;

    uint32_t b0[2], swB[2][2];
#pragma unroll
    for (int jj = 0; jj < 2; jj++) {
        int r = wn + jj * 16 + ((lid >> 4) << 3) + (lid & 7);
        b0[jj] = (uint32_t)r * 256;
        swB[jj][0] = (uint32_t)((2 * r) & 7) << 4;
        swB[jj][1] = (uint32_t)((2 * r + 1) & 7) << 4;
    }
    uint32_t cB = (uint32_t)((lid >> 3) & 1) << 4;

    float acc[4][4][4];
#pragma unroll
    for (int i = 0; i < 4; i++)
#pragma unroll
        for (int j2 = 0; j2 < 4; j2++)
#pragma unroll
            for (int q = 0; q < 4; q++) acc[i][j2][q] = 0.f;

    if (t == 0) {
#pragma unroll
        for (int s = 0; s < NSTAGE; s++) {
            uint32_t dA = base + (uint32_t)s * STAGE_B;
            tma_issue_pair(mb + 8 * s, dA, dA + A_TILE, &mapA, &mapB, s, m0, n0);
        }
    }

    int rd = 0, par = 0;
    for (int i = 0; i < KB128; i++) {
        mbar_wait(mb + 8 * rd, par);
        uint32_t sA = base + (uint32_t)rd * STAGE_B;
        uint32_t sB = sA + A_TILE;

        uint32_t afr[2][16], bfr[2][8];
        // prologue: fragments for kstep 0
        {
            uint32_t q = 0, av = 0;
#pragma unroll
            for (int mt = 0; mt < 4; mt++)
                ldsm4(&afr[0][mt * 4], sA + a0[mt] + q * 128 + ((cA + av) ^ swA[mt][q]));
#pragma unroll
            for (int jj = 0; jj < 2; jj++)
                ldsm4(&bfr[0][jj * 4], sB + b0[jj] + q * 128 + ((cB + av) ^ swB[jj][q]));
        }
#pragma unroll
        for (int s = 0; s < 8; s++) {           // 8 k-steps of 16 within k=128
            int cur = s & 1, nxt = cur ^ 1;
            if (s < 7) {                        // prefetch kstep s+1 fragments
                uint32_t q = (uint32_t)((s + 1) >> 2);
                uint32_t av = (uint32_t)((s + 1) & 3) << 5;
#pragma unroll
                for (int mt = 0; mt < 4; mt++)
                    ldsm4(&afr[nxt][mt * 4], sA + a0[mt] + q * 128 + ((cA + av) ^ swA[mt][q]));
#pragma unroll
                for (int jj = 0; jj < 2; jj++)
                    ldsm4(&bfr[nxt][jj * 4], sB + b0[jj] + q * 128 + ((cB + av) ^ swB[jj][q]));
            }
#pragma unroll
            for (int mt = 0; mt < 4; mt++)
#pragma unroll
                for (int nt = 0; nt < 4; nt++)
                    mma16816(acc[mt][nt], &afr[cur][mt * 4], &bfr[cur][nt * 2]);
        }
        __syncthreads();   // all warps done with stage rd
        if (i + NSTAGE < KB128 && t == 0) {
            uint32_t dA = base + (uint32_t)rd * STAGE_B;
            tma_issue_pair(mb + 8 * rd, dA, dA + A_TILE, &mapA, &mapB,
                           i + NSTAGE, m0, n0);
        }
        rd++; if (rd == NSTAGE) { rd = 0; par ^= 1; }
    }

    // Epilogue: stage [n][m] in smem, then coalesced float4 stores along hw.
    float* so = (float*)sm;
    int g = lid >> 2, tt = lid & 3;
#pragma unroll
    for (int mt = 0; mt < 4; mt++)
#pragma unroll
        for (int nt = 0; nt < 4; nt++) {
            int nl = wn + nt * 8 + 2 * tt;
            int ml = wm + mt * 16 + g;
            so[nl * 128 + ml]           = acc[mt][nt][0];
            so[(nl + 1) * 128 + ml]     = acc[mt][nt][1];
            so[nl * 128 + ml + 8]       = acc[mt][nt][2];
            so[(nl + 1) * 128 + ml + 8] = acc[mt][nt][3];
        }
    __syncthreads();
    int bb2 = m0 >> 10, hw0 = m0 & 1023;
#pragma unroll
    for (int it = 0; it < 16; it++) {
        int idx = t + 256 * it;
        int n = idx >> 5, mq = (idx & 31) * 4;
        float4 v = *(float4*)&so[n * 128 + mq];
        *(float4*)&out[((size_t)bb2 * D_ + n0 + n) * HW_ + hw0 + mq] = v;
    }
}

// ---------------------------------------------------------------------------
// Launch. Output layout: sampled [B*D*HW] | kl [1] | logits [B*HW*C] | log_qy
// ---------------------------------------------------------------------------
typedef CUresult (*EncodeFn)(CUtensorMap*, CUtensorMapDataType, cuuint32_t, void*,
                             const cuuint64_t*, const cuuint64_t*, const cuuint32_t*,
                             const cuuint32_t*, CUtensorMapInterleave, CUtensorMapSwizzle,
                             CUtensorMapL2promotion, CUtensorMapFloatOOBfill);

extern "C" void kernel_launch(void* const* d_in, const int* in_sizes, int n_in,
                              void* d_out, int out_size) {
    const float* x   = (const float*)d_in[0];
    const float* gm  = (const float*)d_in[1];
    const float* emb = (const float*)d_in[2];
    float* out = (float*)d_out;

    const long long N_SAMP = (long long)B_ * D_ * HW_;
    const long long N_LG   = (long long)B_ * HW_ * C_;

    float* logits = nullptr;
    float* logqy  = nullptr;
    float* kl     = nullptr;
    if ((long long)out_size >= N_SAMP + 1 + 2 * N_LG) {
        kl     = out + N_SAMP;
        logits = out + N_SAMP + 1;
        logqy  = logits + N_LG;
    } else if ((long long)out_size >= N_SAMP + 1 + N_LG) {
        kl     = out + N_SAMP;
        logits = out + N_SAMP + 1;
    } else if ((long long)out_size >= N_SAMP + 1) {
        kl = out + N_SAMP;
    }

    static bool attr_done = false;
    if (!attr_done) {
        cudaFuncSetAttribute(k_gemm_tma, cudaFuncAttributeMaxDynamicSharedMemorySize,
                             SMEM_GEMM);
        attr_done = true;
    }

    // Build TMA descriptors (host-side, outside any graph node)
    EncodeFn enc = nullptr;
    cudaDriverEntryPointQueryResult qr;
    cudaGetDriverEntryPointByVersion("cuTensorMapEncodeTiled", (void**)&enc, 12000,
                                     cudaEnableDefault, &qr);
    void* pA = nullptr; void* pB = nullptr;
    cudaGetSymbolAddress(&pA, g_A);
    cudaGetSymbolAddress(&pB, g_B);

    CUtensorMap mA, mB;
    {   // A: [pos][kb64][64 fp16], box loads 2 kb64 rows (k=128)
        cuuint64_t dims[3]   = {64, (cuuint64_t)KB64, (cuuint64_t)P_};
        cuuint64_t strides[2]= {128, (cuuint64_t)KB64 * 128};
        cuuint32_t box[3]    = {64, 2, BM};
        cuuint32_t es[3]     = {1, 1, 1};
        enc(&mA, CU_TENSOR_MAP_DATA_TYPE_FLOAT16, 3, pA, dims, strides, box, es,
            CU_TENSOR_MAP_INTERLEAVE_NONE, CU_TENSOR_MAP_SWIZZLE_128B,
            CU_TENSOR_MAP_L2_PROMOTION_L2_128B, CU_TENSOR_MAP_FLOAT_OOB_FILL_NONE);
    }
    {   // B: [d][kb64][64 fp16], box loads 2 kb64 rows (k=128)
        cuuint64_t dims[3]   = {64, (cuuint64_t)KB64, (cuuint64_t)D_};
        cuuint64_t strides[2]= {128, (cuuint64_t)KB64 * 128};
        cuuint32_t box[3]    = {64, 2, BN};
        cuuint32_t es[3]     = {1, 1, 1};
        enc(&mB, CU_TENSOR_MAP_DATA_TYPE_FLOAT16, 3, pB, dims, strides, box, es,
            CU_TENSOR_MAP_INTERLEAVE_NONE, CU_TENSOR_MAP_SWIZZLE_128B,
            CU_TENSOR_MAP_L2_PROMOTION_L2_128B, CU_TENSOR_MAP_FLOAT_OOB_FILL_NONE);
    }

    k_conv<<<dim3(C_ / 32, D_ / 32), dim3(32, 8)>>>(emb);
    k_stats<<<dim3(16, NCHUNK), 256>>>(x, gm);
    k_combine<<<16, 256>>>(kl);
    k_elem<<<dim3(HW_ / 32, C_ / 64, B_), dim3(32, 8)>>>(x, gm, logits, logqy, kl);
    k_gemm_tma<<<dim3(P_ / BM, D_ / BN), 256, SMEM_GEMM>>>(mA, mB, out);
}